// round 6
// baseline (speedup 1.0000x reference)
#include <cuda_runtime.h>
#include <cuda_fp16.h>
#include <cstdint>
#include <cstddef>

// Problem constants
#define B_   16
#define CIN  512
#define HW   4096
#define G_   8
#define EPSG 1e-5f
#define STILES 32           // HW / 128
#define NTP   36            // triangle tile pairs (8x8 blocks of 64)

// u-GEMM: M=256 x N=128 x K=512, 4-stage cp.async
#define AS_LD 20
#define BS_LD 68
#define A_STG 20480
#define B_STG 8704
#define B_OFF 81920
#define SMEM_GEMM (B_OFF + 4*B_STG)

// Gram: 64x64 tile, K=4096, k-stage 128, 4-stage
#define GR_ROW 272                       // bytes per 64-row (128 halfs + 16 pad)
#define GR_SIDE 17408                    // 64*272
#define GR_STG (2*GR_SIDE)               // 34816
#define SMEM_GRAM (4*GR_STG)             // 139264

// ---------------- device scratch ----------------
__device__ __half g_A16[CIN*CIN];                // Wcomb fp16
__device__ __half g_M16[G_*CIN*CIN];             // Msym per group, fp16 (4 MB)
__device__ __half g_x16[(size_t)B_*CIN*HW];      // x fp16 (67 MB)
__device__ __half g_u[(size_t)B_*CIN*HW];        // u fp16 (67 MB)
__device__ float  g_attp[B_*G_*NTP];
__device__ float  g_sump[B_*G_*STILES];
__device__ float  g_sumsqp[B_*G_*STILES];
__device__ float  g_scale[B_*CIN];
__device__ float  g_bias[B_*CIN];

// ---------------- PTX helpers ----------------
__device__ __forceinline__ uint32_t smem_u32(const void* p) {
    uint32_t a;
    asm("{ .reg .u64 t; cvta.to.shared.u64 t, %1; cvt.u32.u64 %0, t; }" : "=r"(a) : "l"(p));
    return a;
}
__device__ __forceinline__ void cpasync16(uint32_t dst, const void* src) {
    asm volatile("cp.async.cg.shared.global [%0], [%1], 16;" :: "r"(dst), "l"(src) : "memory");
}
#define CP_COMMIT()  asm volatile("cp.async.commit_group;" ::: "memory")
#define CP_WAIT(n)   asm volatile("cp.async.wait_group %0;" :: "n"(n) : "memory")

__device__ __forceinline__ void ldsm4(unsigned* r, uint32_t a) {
    asm volatile("ldmatrix.sync.aligned.m8n8.x4.shared.b16 {%0,%1,%2,%3}, [%4];"
        : "=r"(r[0]), "=r"(r[1]), "=r"(r[2]), "=r"(r[3]) : "r"(a));
}
__device__ __forceinline__ void ldsm4t(unsigned* r, uint32_t a) {
    asm volatile("ldmatrix.sync.aligned.m8n8.x4.trans.shared.b16 {%0,%1,%2,%3}, [%4];"
        : "=r"(r[0]), "=r"(r[1]), "=r"(r[2]), "=r"(r[3]) : "r"(a));
}
__device__ __forceinline__ void mma16(float* c, const unsigned* a, const unsigned* b) {
    asm volatile(
        "mma.sync.aligned.m16n8k16.row.col.f32.f16.f16.f32 "
        "{%0,%1,%2,%3}, {%4,%5,%6,%7}, {%8,%9}, {%0,%1,%2,%3};\n"
        : "+f"(c[0]), "+f"(c[1]), "+f"(c[2]), "+f"(c[3])
        : "r"(a[0]), "r"(a[1]), "r"(a[2]), "r"(a[3]), "r"(b[0]), "r"(b[1]));
}
__device__ __forceinline__ float wred(float v) {
#pragma unroll
    for (int o = 16; o; o >>= 1) v += __shfl_down_sync(0xffffffffu, v, o);
    return v;
}

// ---------------- K1: Wcomb fp16 ----------------
__global__ void k_prepA(const float* __restrict__ Wt, const float* __restrict__ Wz) {
    int r = blockIdx.x;          // 0..511
    int g = r >> 6, o = r & 63;
    __shared__ float wz[32];
    if (threadIdx.x < 32) wz[threadIdx.x] = Wz[(size_t)(g*64 + o)*32 + threadIdx.x];
    __syncthreads();
    for (int i = threadIdx.x; i < CIN; i += blockDim.x) {
        float a = 0.f;
#pragma unroll 8
        for (int c = 0; c < 32; c++)
            a += wz[c] * Wt[(size_t)(g*32 + c)*CIN + i];
        g_A16[(size_t)r*CIN + i] = __float2half(a);
    }
}

// ---------------- K2: Msym[g] = 0.5(Wp_g^T Wg_g + Wg_g^T Wp_g), fp16 ----------------
__global__ void k_prepM(const float* __restrict__ Wp, const float* __restrict__ Wg) {
    extern __shared__ float ms[];
    float* ApI = ms;             // [32][128]
    float* AgJ = ms + 4096;
    float* ApJ = ms + 8192;
    float* AgI = ms + 12288;
    const int ib = blockIdx.x, jb = blockIdx.y, g = blockIdx.z;
    const int tid = threadIdx.x;
    const int lr = tid >> 3, lcb = (tid & 7) * 16;
#pragma unroll
    for (int q = 0; q < 4; q++) {
        int col = lcb + q*4;
        *(float4*)&ApI[lr*128 + col] = *(const float4*)&Wp[(size_t)(32*g + lr)*CIN + ib*128 + col];
        *(float4*)&AgJ[lr*128 + col] = *(const float4*)&Wg[(size_t)(32*g + lr)*CIN + jb*128 + col];
        *(float4*)&ApJ[lr*128 + col] = *(const float4*)&Wp[(size_t)(32*g + lr)*CIN + jb*128 + col];
        *(float4*)&AgI[lr*128 + col] = *(const float4*)&Wg[(size_t)(32*g + lr)*CIN + ib*128 + col];
    }
    __syncthreads();
    const int i0 = (tid >> 4) * 8, j0 = (tid & 15) * 8;
    float m[8][8];
#pragma unroll
    for (int ii = 0; ii < 8; ii++)
#pragma unroll
        for (int jj = 0; jj < 8; jj++) m[ii][jj] = 0.f;
    for (int c = 0; c < 32; c++) {
        float api[8], agj[8], apj[8], agi[8];
#pragma unroll
        for (int q = 0; q < 8; q++) {
            api[q] = ApI[c*128 + i0 + q];
            agj[q] = AgJ[c*128 + j0 + q];
            apj[q] = ApJ[c*128 + j0 + q];
            agi[q] = AgI[c*128 + i0 + q];
        }
#pragma unroll
        for (int ii = 0; ii < 8; ii++)
#pragma unroll
            for (int jj = 0; jj < 8; jj++)
                m[ii][jj] += api[ii]*agj[jj] + apj[jj]*agi[ii];
    }
#pragma unroll
    for (int ii = 0; ii < 8; ii++)
#pragma unroll
        for (int jj = 0; jj < 8; jj += 2) {
            __half2 h = __floats2half2_rn(0.5f*m[ii][jj], 0.5f*m[ii][jj+1]);
            *(__half2*)&g_M16[((size_t)g*CIN + ib*128 + i0 + ii)*CIN + jb*128 + j0 + jj] = h;
        }
}

// ---------------- K3: x -> fp16 ----------------
__global__ void k_prepX(const float* __restrict__ x) {
    size_t i = (size_t)blockIdx.x * blockDim.x + threadIdx.x;
    float4 v = ((const float4*)x)[i];
    __half2* d = (__half2*)g_x16;
    d[2*i]     = __floats2half2_rn(v.x, v.y);
    d[2*i + 1] = __floats2half2_rn(v.z, v.w);
}

// ---------------- K4: u = Wcomb @ x (fp16) + GN partials ----------------
__global__ void __launch_bounds__(256, 1)
k_gemm() {
    extern __shared__ char smem[];
    const uint32_t sb = smem_u32(smem);
    __shared__ float rbuf[16];

    const int tid  = threadIdx.x;
    const int lane = tid & 31, warp = tid >> 5;
    const int wm = warp >> 1, wn = warp & 1;     // 4m x 2n warps; warp tile 64x64
    const int stile = blockIdx.x, yb = blockIdx.y, b = blockIdx.z;
    const int scol0 = stile * 128;

    const int am = (tid >> 2), ac4 = tid & 3;
    const int bk = (tid >> 4), bn16 = tid & 15;
    const __half* asrc[4];
#pragma unroll
    for (int p = 0; p < 4; p++)
        asrc[p] = g_A16 + ((size_t)yb*256 + am + p*64)*CIN + ac4*8;
    const __half* bsrc[2];
#pragma unroll
    for (int p = 0; p < 2; p++)
        bsrc[p] = g_x16 + ((size_t)b*CIN + bk + p*16)*HW + scol0 + bn16*8;
    const uint32_t adst = sb + am*80 + ac4*16;
    const uint32_t bdst = sb + B_OFF + bk*272 + bn16*16;

    auto issue = [&](int s) {
        if (s < 16) {
            const int i = s & 3;
#pragma unroll
            for (int p = 0; p < 4; p++)
                cpasync16(adst + i*A_STG + p*64*80, asrc[p] + s*32);
#pragma unroll
            for (int p = 0; p < 2; p++)
                cpasync16(bdst + i*B_STG + p*16*272, bsrc[p] + (size_t)s*32*HW);
        }
        CP_COMMIT();
    };

    const int a_row = wm*64 + (lane & 15);
    const int a_kw  = (lane >> 4) * 4;
    const int b_k   = lane & 15;
    const int b_w   = (lane >> 4) * 4;

    float acc[4][8][4];
#pragma unroll
    for (int mt = 0; mt < 4; mt++)
#pragma unroll
        for (int nt = 0; nt < 8; nt++)
#pragma unroll
            for (int i = 0; i < 4; i++) acc[mt][nt][i] = 0.f;

    issue(0);
    issue(1);

    for (int s = 0; s < 16; s++) {
        issue(s + 2);
        CP_WAIT(2);
        __syncthreads();
        const uint32_t abuf = sb + (s & 3)*A_STG;
        const uint32_t bbuf = sb + B_OFF + (s & 3)*B_STG;
#pragma unroll
        for (int ks = 0; ks < 2; ks++) {
            unsigned af[4][4], bf[4][4];
#pragma unroll
            for (int mt = 0; mt < 4; mt++)
                ldsm4(af[mt], abuf + ((a_row + mt*16)*AS_LD + ks*8 + a_kw)*4);
#pragma unroll
            for (int ng = 0; ng < 4; ng++)
                ldsm4t(bf[ng], bbuf + ((ks*16 + b_k)*BS_LD + wn*32 + ng*8 + b_w)*4);
#pragma unroll
            for (int mt = 0; mt < 4; mt++)
#pragma unroll
                for (int ng = 0; ng < 4; ng++) {
                    mma16(acc[mt][2*ng],     af[mt], &bf[ng][0]);
                    mma16(acc[mt][2*ng + 1], af[mt], &bf[ng][2]);
                }
        }
    }
    CP_WAIT(0);
    __syncthreads();

    const int lr = lane >> 2, lc2 = (lane & 3)*2;
    float s1 = 0.f, s2 = 0.f;
    const size_t ub = ((size_t)b*CIN + yb*256 + wm*64)*HW + scol0 + wn*64;
#pragma unroll
    for (int mt = 0; mt < 4; mt++)
#pragma unroll
        for (int nt = 0; nt < 8; nt++)
#pragma unroll
            for (int i2 = 0; i2 < 2; i2++) {
                float v0 = acc[mt][nt][i2*2], v1 = acc[mt][nt][i2*2 + 1];
                int r = mt*16 + lr + i2*8;
                int c = nt*8 + lc2;
                *(__half2*)&g_u[ub + (size_t)r*HW + c] = __floats2half2_rn(v0, v1);
                s1 += v0 + v1;
                s2 += v0*v0 + v1*v1;
            }
    s1 = wred(s1); s2 = wred(s2);
    if (lane == 0) { rbuf[wm*2 + wn] = s1; rbuf[8 + wm*2 + wn] = s2; }
    __syncthreads();
    if (tid < 4) {
        int g = yb*4 + tid;
        g_sump[(b*G_ + g)*STILES + stile]   = rbuf[tid*2] + rbuf[tid*2 + 1];
        g_sumsqp[(b*G_ + g)*STILES + stile] = rbuf[8 + tid*2] + rbuf[8 + tid*2 + 1];
    }
}

// ---------------- K5: Gram-tile + Msym contraction -> att partials ----------------
// S tile (64x64) = X[iblk] @ X[jblk]^T over K=4096; att_part = <S, Msym_g> (x2 off-diag)
__global__ void __launch_bounds__(256, 1)
k_gram() {
    extern __shared__ char smem[];
    const uint32_t sb = smem_u32(smem);
    __shared__ float ssum[64];

    const int tid  = threadIdx.x;
    const int lane = tid & 31, warp = tid >> 5;
    const int wm = warp >> 1, wn = warp & 1;     // warp tile 16m x 32n
    const int tp = blockIdx.x, b = blockIdx.y;

    // triangle pair index -> (iblk >= jblk)
    int ib = 0, rem = tp;
    while (rem > ib) { rem -= (ib + 1); ib++; }
    const int jb = rem;
    const int chi = ib*64, chj = jb*64;

    // loaders: 8 cp16/thread/stage (4 Xi + 4 Xj)
    const int row = tid >> 2;
    const __half* isrc = g_x16 + ((size_t)b*CIN + chi + row)*HW;
    const __half* jsrc = g_x16 + ((size_t)b*CIN + chj + row)*HW;
    const uint32_t idst = sb + row*GR_ROW;
    const uint32_t jdst = sb + GR_SIDE + row*GR_ROW;

    auto issue = [&](int s) {
        if (s < 32) {
            const int st = (s & 3)*GR_STG;
            const int kb = s*128;
#pragma unroll
            for (int p = 0; p < 4; p++) {
                int ch = (tid & 3)*4 + p;      // 0..15 16B chunks
                cpasync16(idst + st + ch*16, isrc + kb + ch*8);
                cpasync16(jdst + st + ch*16, jsrc + kb + ch*8);
            }
        }
        CP_COMMIT();
    };

    const int l15 = lane & 15, lk = (lane >> 4) * 16;

    float acc[4][4];
#pragma unroll
    for (int nt = 0; nt < 4; nt++)
#pragma unroll
        for (int i = 0; i < 4; i++) acc[nt][i] = 0.f;

    issue(0);
    issue(1);

    for (int s = 0; s < 32; s++) {
        issue(s + 2);
        CP_WAIT(2);
        __syncthreads();
        const uint32_t xi = sb + (s & 3)*GR_STG;
        const uint32_t xj = xi + GR_SIDE;
#pragma unroll
        for (int ks = 0; ks < 8; ks++) {
            unsigned af[4], bf[2][4];
            ldsm4(af, xi + (wm*16 + l15)*GR_ROW + ks*32 + lk);
#pragma unroll
            for (int ng = 0; ng < 2; ng++)
                ldsm4(bf[ng], xj + (wn*32 + ng*16 + l15)*GR_ROW + ks*32 + lk);
            // B from n-major rows (non-trans): n0-7 -> {r0,r2}, n8-15 -> {r1,r3}
            unsigned b0[2] = { bf[0][0], bf[0][2] };
            unsigned b1[2] = { bf[0][1], bf[0][3] };
            unsigned b2[2] = { bf[1][0], bf[1][2] };
            unsigned b3[2] = { bf[1][1], bf[1][3] };
            mma16(acc[0], af, b0);
            mma16(acc[1], af, b1);
            mma16(acc[2], af, b2);
            mma16(acc[3], af, b3);
        }
    }
    CP_WAIT(0);
    __syncthreads();

    // contract with Msym tiles (fp16)
    const int lr = lane >> 2, lc2 = (lane & 3)*2;
    const float fac = (ib == jb) ? 1.f : 2.f;
    float tsum[8];
#pragma unroll
    for (int g = 0; g < 8; g++) tsum[g] = 0.f;
#pragma unroll
    for (int g = 0; g < 8; g++) {
        const __half* mg = g_M16 + (size_t)g*CIN*CIN;
#pragma unroll
        for (int nt = 0; nt < 4; nt++)
#pragma unroll
            for (int i2 = 0; i2 < 2; i2++) {
                int r = chi + wm*16 + lr + i2*8;
                int c = chj + wn*32 + nt*8 + lc2;
                float2 m = __half22float2(*(const __half2*)&mg[(size_t)r*CIN + c]);
                tsum[g] += acc[nt][i2*2]*m.x + acc[nt][i2*2 + 1]*m.y;
            }
    }
#pragma unroll
    for (int g = 0; g < 8; g++) {
        float v = wred(tsum[g]);
        if (lane == 0) ssum[warp*8 + g] = v;
    }
    __syncthreads();
    if (tid < 8) {
        float a = 0.f;
#pragma unroll
        for (int w2 = 0; w2 < 8; w2++) a += ssum[w2*8 + tid];
        g_attp[(b*G_ + tid)*NTP + tp] = a * fac;
    }
}

// ---------------- K6: fold att + GN into per-(b,c) scale/bias ----------------
__global__ void k_stats(const float* __restrict__ gamma, const float* __restrict__ beta) {
    const int b = blockIdx.x, tid = threadIdx.x;
    const int w = tid >> 5, lane = tid & 31;
    __shared__ float sS[8], sMu[8];
    float sm = g_sump[(b*G_ + w)*STILES + lane];
    float sq = g_sumsqp[(b*G_ + w)*STILES + lane];
    float at = g_attp[(b*G_ + w)*NTP + lane];
    if (lane < NTP - 32) at += g_attp[(b*G_ + w)*NTP + 32 + lane];
    sm = wred(sm); sq = wred(sq); at = wred(at);
    if (lane == 0) {
        const float n = 64.0f * 4096.0f;
        float mu  = sm / n;
        float var = fmaxf(sq / n - mu*mu, 0.f);
        float rstd = rsqrtf(at*at*var + EPSG);
        sS[w]  = at * rstd;
        sMu[w] = mu;
    }
    __syncthreads();
#pragma unroll
    for (int q = 0; q < 2; q++) {
        int c = tid + q*256;
        int g = c >> 6;
        float S = sS[g], mu = sMu[g];
        g_scale[b*CIN + c] = S * gamma[c];
        g_bias[b*CIN + c]  = beta[c] - S * mu * gamma[c];
    }
}

// ---------------- K7: out = scale*u + bias + x (x from fp16) ----------------
__global__ void k_final(float* __restrict__ out) {
    size_t i = (size_t)blockIdx.x * blockDim.x + threadIdx.x;   // float4 index
    size_t e = i << 2;
    int b = (int)(e >> 21);
    int c = (int)((e >> 12) & 511);
    float sc = g_scale[b*CIN + c];
    float bi = g_bias[b*CIN + c];
    const __half2* up = (const __half2*)g_u;
    const __half2* xp = (const __half2*)g_x16;
    float2 u0 = __half22float2(up[2*i]);
    float2 u1 = __half22float2(up[2*i + 1]);
    float2 x0 = __half22float2(xp[2*i]);
    float2 x1 = __half22float2(xp[2*i + 1]);
    float4 o;
    o.x = fmaf(sc, u0.x, bi + x0.x);
    o.y = fmaf(sc, u0.y, bi + x0.y);
    o.z = fmaf(sc, u1.x, bi + x1.x);
    o.w = fmaf(sc, u1.y, bi + x1.y);
    ((float4*)out)[i] = o;
}

// ---------------- launch ----------------
extern "C" void kernel_launch(void* const* d_in, const int* in_sizes, int n_in,
                              void* d_out, int out_size) {
    const float* x     = (const float*)d_in[0];
    const float* Wt    = (const float*)d_in[1];
    const float* Wp    = (const float*)d_in[2];
    const float* Wg    = (const float*)d_in[3];
    const float* Wz    = (const float*)d_in[4];
    const float* gamma = (const float*)d_in[5];
    const float* beta  = (const float*)d_in[6];
    float* out = (float*)d_out;

    cudaFuncSetAttribute(k_gemm, cudaFuncAttributeMaxDynamicSharedMemorySize, SMEM_GEMM);
    cudaFuncSetAttribute(k_gram, cudaFuncAttributeMaxDynamicSharedMemorySize, SMEM_GRAM);
    cudaFuncSetAttribute(k_prepM, cudaFuncAttributeMaxDynamicSharedMemorySize, 65536);

    k_prepA<<<512, 128>>>(Wt, Wz);
    k_prepM<<<dim3(4, 4, G_), 256, 65536>>>(Wp, Wg);
    k_prepX<<<32768, 256>>>(x);
    k_gemm<<<dim3(STILES, 2, B_), 256, SMEM_GEMM>>>();
    k_gram<<<dim3(NTP, B_), 256, SMEM_GRAM>>>();
    k_stats<<<B_, 256>>>(gamma, beta);
    k_final<<<32768, 256>>>(out);
}

// round 7
// speedup vs baseline: 1.2531x; 1.2531x over previous
#include <cuda_runtime.h>
#include <cuda_fp16.h>
#include <cstdint>
#include <cstddef>

// Problem constants
#define B_   16
#define CIN  512
#define HW   4096
#define G_   8
#define EPSG 1e-5f
#define STILES 32           // HW / 128

// GEMM: CTA tile M=128, N=128, K=512, k-stage 32, 4-deep cp.async ring, 2 CTA/SM
#define AS_LD 20            // A k-row stride in words (16 data + 4 pad)
#define BS_LD 68            // B k-row stride in words (64 data + 4 pad)
#define A_STG 10240         // 128 rows * 80 B
#define B_STG 8704          // 32 k-rows * 272 B
#define STG   18944
#define SMEM_GEMM (4*STG)   // 75776 -> 2 CTAs/SM
#define DMP_LD 130          // att g-dump row stride (floats), even

// ---------------- device scratch ----------------
// rows 0..511: Wcomb ; rows 512..1023: 4 chunks of [Wp(64);Wg(64)]
__device__ __half g_AW[1024*CIN];
__device__ __half g_x16[(size_t)B_*CIN*HW];      // x fp16 (67 MB)
__device__ __half g_u[(size_t)B_*CIN*HW];        // u fp16 (67 MB)
__device__ float  g_attp[B_*G_*STILES];
__device__ float  g_sump[B_*G_*STILES];
__device__ float  g_sumsqp[B_*G_*STILES];
__device__ float  g_scale[B_*CIN];
__device__ float  g_bias[B_*CIN];

// ---------------- PTX helpers ----------------
__device__ __forceinline__ uint32_t smem_u32(const void* p) {
    uint32_t a;
    asm("{ .reg .u64 t; cvta.to.shared.u64 t, %1; cvt.u32.u64 %0, t; }" : "=r"(a) : "l"(p));
    return a;
}
__device__ __forceinline__ void cpasync16(uint32_t dst, const void* src) {
    asm volatile("cp.async.cg.shared.global [%0], [%1], 16;" :: "r"(dst), "l"(src) : "memory");
}
#define CP_COMMIT()  asm volatile("cp.async.commit_group;" ::: "memory")
#define CP_WAIT(n)   asm volatile("cp.async.wait_group %0;" :: "n"(n) : "memory")

__device__ __forceinline__ void ldsm4(unsigned* r, uint32_t a) {
    asm volatile("ldmatrix.sync.aligned.m8n8.x4.shared.b16 {%0,%1,%2,%3}, [%4];"
        : "=r"(r[0]), "=r"(r[1]), "=r"(r[2]), "=r"(r[3]) : "r"(a));
}
__device__ __forceinline__ void ldsm4t(unsigned* r, uint32_t a) {
    asm volatile("ldmatrix.sync.aligned.m8n8.x4.trans.shared.b16 {%0,%1,%2,%3}, [%4];"
        : "=r"(r[0]), "=r"(r[1]), "=r"(r[2]), "=r"(r[3]) : "r"(a));
}
__device__ __forceinline__ void mma16(float* c, const unsigned* a, const unsigned* b) {
    asm volatile(
        "mma.sync.aligned.m16n8k16.row.col.f32.f16.f16.f32 "
        "{%0,%1,%2,%3}, {%4,%5,%6,%7}, {%8,%9}, {%0,%1,%2,%3};\n"
        : "+f"(c[0]), "+f"(c[1]), "+f"(c[2]), "+f"(c[3])
        : "r"(a[0]), "r"(a[1]), "r"(a[2]), "r"(a[3]), "r"(b[0]), "r"(b[1]));
}
__device__ __forceinline__ float wred(float v) {
#pragma unroll
    for (int o = 16; o; o >>= 1) v += __shfl_down_sync(0xffffffffu, v, o);
    return v;
}

// ---------------- K1: build g_AW (Wcomb | 4x[Wp;Wg]) fp16 ----------------
__global__ void k_prepA(const float* __restrict__ Wt, const float* __restrict__ Wp,
                        const float* __restrict__ Wg, const float* __restrict__ Wz) {
    const int r = blockIdx.x;          // 0..1023
    __half* dst = g_AW + (size_t)r*CIN;
    if (r < 512) {
        int g = r >> 6, o = r & 63;
        __shared__ float wz[32];
        if (threadIdx.x < 32) wz[threadIdx.x] = Wz[(size_t)(g*64 + o)*32 + threadIdx.x];
        __syncthreads();
        for (int i = threadIdx.x; i < CIN; i += blockDim.x) {
            float a = 0.f;
#pragma unroll 8
            for (int c = 0; c < 32; c++)
                a += wz[c] * Wt[(size_t)(g*32 + c)*CIN + i];
            dst[i] = __float2half(a);
        }
    } else {
        int idx = r - 512;
        int chunk = idx >> 7, row = idx & 127;
        const float* src = (row < 64) ? Wp + (size_t)(chunk*64 + row)*CIN
                                      : Wg + (size_t)(chunk*64 + row - 64)*CIN;
        for (int i = threadIdx.x; i < CIN; i += blockDim.x)
            dst[i] = __float2half(src[i]);
    }
}

// ---------------- K2: x -> fp16 ----------------
__global__ void k_prepX(const float* __restrict__ x) {
    size_t i = (size_t)blockIdx.x * blockDim.x + threadIdx.x;
    float4 v = ((const float4*)x)[i];
    __half2* d = (__half2*)g_x16;
    d[2*i]     = __floats2half2_rn(v.x, v.y);
    d[2*i + 1] = __floats2half2_rn(v.z, v.w);
}

// ---------------- K3: unified GEMM ----------------
// yy<4: C = Wcomb[yy*128..] @ X  -> u + GN partials
// yy>=4: C = [Wp;Wg](chunk yy-4) @ X -> att partials
__global__ void __launch_bounds__(256, 2)
k_gemm() {
    extern __shared__ char smem[];
    const uint32_t sb = smem_u32(smem);
    __shared__ float rbuf[16];

    const int tid  = threadIdx.x;
    const int lane = tid & 31, warp = tid >> 5;
    const int wm = warp >> 1, wn = warp & 1;     // 4m x 2n warps; warp tile 32m x 64n
    const int stile = blockIdx.x, yy = blockIdx.y, b = blockIdx.z;
    const int scol0 = stile * 128;

    // cp.async loaders
    const int arow = tid >> 1, ah = tid & 1;     // A: 2 chunks/thread
    const __half* asrc = g_AW + ((size_t)yy*128 + arow)*CIN + ah*16;
    const uint32_t adst = sb + arow*80 + ah*32;
    const int bk = (tid >> 4), bn16 = tid & 15;  // B: 2 chunks/thread
    const __half* bsrc0 = g_x16 + ((size_t)b*CIN + bk)*HW + scol0 + bn16*8;
    const uint32_t bdst = sb + A_STG + bk*272 + bn16*16;

    auto issue = [&](int s) {
        if (s < 16) {
            const int st = (s & 3)*STG;
            cpasync16(adst + st,      asrc + s*32);
            cpasync16(adst + st + 16, asrc + s*32 + 8);
            cpasync16(bdst + st,            bsrc0 + (size_t)s*32*HW);
            cpasync16(bdst + st + 16*272,   bsrc0 + (size_t)(s*32 + 16)*HW);
        }
        CP_COMMIT();
    };

    const int a_row = wm*32 + (lane & 15);
    const int a_kw  = (lane >> 4) * 4;
    const int b_k   = lane & 15;
    const int b_w   = (lane >> 4) * 4;

    float acc[2][8][4];
#pragma unroll
    for (int mt = 0; mt < 2; mt++)
#pragma unroll
        for (int nt = 0; nt < 8; nt++)
#pragma unroll
            for (int i = 0; i < 4; i++) acc[mt][nt][i] = 0.f;

    issue(0);
    issue(1);

    for (int s = 0; s < 16; s++) {
        issue(s + 2);
        CP_WAIT(2);
        __syncthreads();
        const uint32_t abuf = sb + (s & 3)*STG;
        const uint32_t bbuf = abuf + A_STG;
#pragma unroll
        for (int ks = 0; ks < 2; ks++) {
            unsigned af[2][4], bf[4][4];
#pragma unroll
            for (int mt = 0; mt < 2; mt++)
                ldsm4(af[mt], abuf + ((a_row + mt*16)*AS_LD + ks*8 + a_kw)*4);
#pragma unroll
            for (int ng = 0; ng < 4; ng++)
                ldsm4t(bf[ng], bbuf + ((ks*16 + b_k)*BS_LD + wn*32 + ng*8 + b_w)*4);
#pragma unroll
            for (int mt = 0; mt < 2; mt++)
#pragma unroll
                for (int ng = 0; ng < 4; ng++) {
                    mma16(acc[mt][2*ng],     af[mt], &bf[ng][0]);
                    mma16(acc[mt][2*ng + 1], af[mt], &bf[ng][2]);
                }
        }
    }
    CP_WAIT(0);
    __syncthreads();

    const int lr = lane >> 2, lc2 = (lane & 3)*2;

    if (yy < 4) {
        // ---- u epilogue: channels yy*128 + wm*32 + ... ; GN group = yy*2 + (wm>>1) ----
        float s1 = 0.f, s2 = 0.f;
        const size_t ub = ((size_t)b*CIN + yy*128 + wm*32)*HW + scol0 + wn*64;
#pragma unroll
        for (int mt = 0; mt < 2; mt++)
#pragma unroll
            for (int nt = 0; nt < 8; nt++)
#pragma unroll
                for (int i2 = 0; i2 < 2; i2++) {
                    float v0 = acc[mt][nt][i2*2], v1 = acc[mt][nt][i2*2 + 1];
                    int r = mt*16 + lr + i2*8;
                    int c = nt*8 + lc2;
                    *(__half2*)&g_u[ub + (size_t)r*HW + c] = __floats2half2_rn(v0, v1);
                    s1 += v0 + v1;
                    s2 += v0*v0 + v1*v1;
                }
        s1 = wred(s1); s2 = wred(s2);
        if (lane == 0) { rbuf[warp] = s1; rbuf[8 + warp] = s2; }
        __syncthreads();
        if (tid < 2) {
            int g = yy*2 + tid;
            float ss = rbuf[tid*4] + rbuf[tid*4+1] + rbuf[tid*4+2] + rbuf[tid*4+3];
            float qq = rbuf[8+tid*4] + rbuf[8+tid*4+1] + rbuf[8+tid*4+2] + rbuf[8+tid*4+3];
            g_sump[(b*G_ + g)*STILES + stile]   = ss;
            g_sumsqp[(b*G_ + g)*STILES + stile] = qq;
        }
    } else {
        // ---- att epilogue: rows 0-63 = p, 64-127 = g ; pair warp wm <-> wm+2 ----
        const int yc = yy - 4;
        float* dmp = (float*)smem;   // [64][DMP_LD]
        if (wm >= 2) {
#pragma unroll
            for (int mt = 0; mt < 2; mt++)
#pragma unroll
                for (int nt = 0; nt < 8; nt++)
#pragma unroll
                    for (int i2 = 0; i2 < 2; i2++) {
                        int r = (wm - 2)*32 + mt*16 + lr + i2*8;
                        int c = wn*64 + nt*8 + lc2;
                        *(float2*)&dmp[r*DMP_LD + c] =
                            make_float2(acc[mt][nt][i2*2], acc[mt][nt][i2*2+1]);
                    }
        }
        __syncthreads();
        if (wm < 2) {
            float pg = 0.f;
#pragma unroll
            for (int mt = 0; mt < 2; mt++)
#pragma unroll
                for (int nt = 0; nt < 8; nt++)
#pragma unroll
                    for (int i2 = 0; i2 < 2; i2++) {
                        int r = wm*32 + mt*16 + lr + i2*8;
                        int c = wn*64 + nt*8 + lc2;
                        pg += acc[mt][nt][i2*2]     * dmp[r*DMP_LD + c]
                            + acc[mt][nt][i2*2 + 1] * dmp[r*DMP_LD + c + 1];
                    }
            pg = wred(pg);
            if (lane == 0) rbuf[warp] = pg;   // warps 0..3 (wm 0,1 x wn 0,1)
        }
        __syncthreads();
        if (tid < 2) {
            // warp ids: wm*2 + wn -> wm0: {0,1}, wm1: {2,3}; group = yc*2 + wm
            float a = rbuf[tid*2] + rbuf[tid*2 + 1];
            g_attp[(b*G_ + yc*2 + tid)*STILES + stile] = a;
        }
    }
}

// ---------------- K4: fold att + GN into per-(b,c) scale/bias ----------------
__global__ void k_stats(const float* __restrict__ gamma, const float* __restrict__ beta) {
    const int b = blockIdx.x, tid = threadIdx.x;
    const int w = tid >> 5, lane = tid & 31;
    __shared__ float sS[8], sMu[8];
    float sm = g_sump[(b*G_ + w)*STILES + lane];
    float sq = g_sumsqp[(b*G_ + w)*STILES + lane];
    float at = g_attp[(b*G_ + w)*STILES + lane];
    sm = wred(sm); sq = wred(sq); at = wred(at);
    if (lane == 0) {
        const float n = 64.0f * 4096.0f;
        float mu  = sm / n;
        float var = fmaxf(sq / n - mu*mu, 0.f);
        float rstd = rsqrtf(at*at*var + EPSG);
        sS[w]  = at * rstd;
        sMu[w] = mu;
    }
    __syncthreads();
#pragma unroll
    for (int q = 0; q < 2; q++) {
        int c = tid + q*256;
        int g = c >> 6;
        float S = sS[g], mu = sMu[g];
        g_scale[b*CIN + c] = S * gamma[c];
        g_bias[b*CIN + c]  = beta[c] - S * mu * gamma[c];
    }
}

// ---------------- K5: out = scale*u + bias + x (x from fp16) ----------------
__global__ void k_final(float* __restrict__ out) {
    size_t i = (size_t)blockIdx.x * blockDim.x + threadIdx.x;   // float4 index
    size_t e = i << 2;
    int b = (int)(e >> 21);
    int c = (int)((e >> 12) & 511);
    float sc = g_scale[b*CIN + c];
    float bi = g_bias[b*CIN + c];
    const __half2* up = (const __half2*)g_u;
    const __half2* xp = (const __half2*)g_x16;
    float2 u0 = __half22float2(up[2*i]);
    float2 u1 = __half22float2(up[2*i + 1]);
    float2 x0 = __half22float2(xp[2*i]);
    float2 x1 = __half22float2(xp[2*i + 1]);
    float4 o;
    o.x = fmaf(sc, u0.x, bi + x0.x);
    o.y = fmaf(sc, u0.y, bi + x0.y);
    o.z = fmaf(sc, u1.x, bi + x1.x);
    o.w = fmaf(sc, u1.y, bi + x1.y);
    ((float4*)out)[i] = o;
}

// ---------------- launch ----------------
extern "C" void kernel_launch(void* const* d_in, const int* in_sizes, int n_in,
                              void* d_out, int out_size) {
    const float* x     = (const float*)d_in[0];
    const float* Wt    = (const float*)d_in[1];
    const float* Wp    = (const float*)d_in[2];
    const float* Wg    = (const float*)d_in[3];
    const float* Wz    = (const float*)d_in[4];
    const float* gamma = (const float*)d_in[5];
    const float* beta  = (const float*)d_in[6];
    float* out = (float*)d_out;

    cudaFuncSetAttribute(k_gemm, cudaFuncAttributeMaxDynamicSharedMemorySize, SMEM_GEMM);

    k_prepA<<<1024, 128>>>(Wt, Wp, Wg, Wz);
    k_prepX<<<32768, 256>>>(x);
    k_gemm<<<dim3(STILES, 8, B_), 256, SMEM_GEMM>>>();
    k_stats<<<B_, 256>>>(gamma, beta);
    k_final<<<32768, 256>>>(out);
}